// round 7
// baseline (speedup 1.0000x reference)
#include <cuda_runtime.h>
#include <cuda_fp16.h>

typedef __half fp16;

#define B_ 2
#define S_ 4096
#define D_ 512
#define M_ (B_ * S_)

// ---------------- scratch (fp16 hi/lo everywhere) ----------------
__device__ fp16 g_xh[(size_t)M_ * D_];
__device__ fp16 g_xl[(size_t)M_ * D_];
__device__ fp16 g_wh[4][D_ * D_];
__device__ fp16 g_wl[4][D_ * D_];
__device__ fp16 g_qh[(size_t)M_ * D_];
__device__ fp16 g_ql[(size_t)M_ * D_];
__device__ fp16 g_kh[(size_t)M_ * D_];
__device__ fp16 g_kl[(size_t)M_ * D_];
__device__ fp16 g_vf[(size_t)M_ * D_];
__device__ fp16 g_ch[(size_t)M_ * D_];
__device__ fp16 g_cl[(size_t)M_ * D_];

// ---------------- ptx helpers ----------------
__device__ __forceinline__ unsigned smaddr(const void* p) {
    return (unsigned)__cvta_generic_to_shared(p);
}
__device__ __forceinline__ void ldsm4(unsigned* r, unsigned a) {
    asm volatile("ldmatrix.sync.aligned.m8n8.x4.shared.b16 {%0,%1,%2,%3},[%4];"
                 : "=r"(r[0]), "=r"(r[1]), "=r"(r[2]), "=r"(r[3]) : "r"(a));
}
__device__ __forceinline__ void ldsm2(unsigned* r, unsigned a) {
    asm volatile("ldmatrix.sync.aligned.m8n8.x2.shared.b16 {%0,%1},[%2];"
                 : "=r"(r[0]), "=r"(r[1]) : "r"(a));
}
__device__ __forceinline__ void ldsm2t(unsigned* r, unsigned a) {
    asm volatile("ldmatrix.sync.aligned.m8n8.x2.trans.shared.b16 {%0,%1},[%2];"
                 : "=r"(r[0]), "=r"(r[1]) : "r"(a));
}
__device__ __forceinline__ void mma16816h(float* c, const unsigned* a, const unsigned* b) {
    asm volatile(
        "mma.sync.aligned.m16n8k16.row.col.f32.f16.f16.f32 "
        "{%0,%1,%2,%3},{%4,%5,%6,%7},{%8,%9},{%0,%1,%2,%3};"
        : "+f"(c[0]), "+f"(c[1]), "+f"(c[2]), "+f"(c[3])
        : "r"(a[0]), "r"(a[1]), "r"(a[2]), "r"(a[3]), "r"(b[0]), "r"(b[1]));
}
__device__ __forceinline__ void cpa16(unsigned d, const void* g) {
    asm volatile("cp.async.cg.shared.global [%0], [%1], 16;" :: "r"(d), "l"(g));
}
__device__ __forceinline__ void cpcommit() { asm volatile("cp.async.commit_group;"); }
__device__ __forceinline__ void cpwait0()  { asm volatile("cp.async.wait_group 0;" ::: "memory"); }

// ---------------- split fp32 -> fp16 hi/lo ----------------
__global__ __launch_bounds__(256) void split_kernel(
    const float* __restrict__ in, fp16* __restrict__ hi, fp16* __restrict__ lo, int n)
{
    int i = blockIdx.x * 256 + threadIdx.x;
    if (i < n) {
        float v = in[i];
        fp16 h = __float2half_rn(v);
        hi[i] = h;
        lo[i] = __float2half_rn(v - __half2float(h));
    }
}

// ---------------- projection GEMM: C[M,512] = A[M,512] @ W[512,512]^T --------
// 3-term fp16 mma. mode 0: fp16 hi/lo out. mode 1: relu + fp32 out. mode 2: fp16 out.
__global__ __launch_bounds__(256) void gemm_proj(
    const fp16* __restrict__ Ah, const fp16* __restrict__ Al,
    const fp16* __restrict__ Wh, const fp16* __restrict__ Wl,
    fp16* __restrict__ Ch, fp16* __restrict__ Cl,
    float* __restrict__ Cf, fp16* __restrict__ Cfh, int mode)
{
    __shared__ fp16 sAh[128 * 40], sAl[128 * 40], sWh[64 * 40], sWl[64 * 40];

    const int tid = threadIdx.x, lane = tid & 31, warp = tid >> 5;
    const int m0 = blockIdx.y * 128, n0 = blockIdx.x * 64;
    const int wm = warp >> 1, wn = warp & 1;

    float acc[2][4][4];
#pragma unroll
    for (int a = 0; a < 2; a++)
#pragma unroll
        for (int b = 0; b < 4; b++)
#pragma unroll
            for (int c = 0; c < 4; c++) acc[a][b][c] = 0.0f;

    for (int k0 = 0; k0 < 512; k0 += 32) {
        __syncthreads();
#pragma unroll
        for (int j = 0; j < 4; j++) {
            int u = tid + j * 256;
            int half = u >> 9, rem = u & 511;
            int row = rem >> 2, c4 = rem & 3;
            const fp16* src = (half ? Al : Ah) + (size_t)(m0 + row) * 512 + k0 + c4 * 8;
            fp16* dst = (half ? sAl : sAh) + row * 40 + c4 * 8;
            *(uint4*)dst = *(const uint4*)src;
        }
#pragma unroll
        for (int j = 0; j < 2; j++) {
            int u = tid + j * 256;
            int half = u >> 8, rem = u & 255;
            int row = rem >> 2, c4 = rem & 3;
            const fp16* src = (half ? Wl : Wh) + (size_t)(n0 + row) * 512 + k0 + c4 * 8;
            fp16* dst = (half ? sWl : sWh) + row * 40 + c4 * 8;
            *(uint4*)dst = *(const uint4*)src;
        }
        __syncthreads();

#pragma unroll
        for (int kc = 0; kc < 2; kc++) {
            unsigned ah[2][4], al[2][4];
#pragma unroll
            for (int mi = 0; mi < 2; mi++) {
                int r = wm * 32 + mi * 16 + (lane & 15);
                int cc = kc * 16 + (lane >> 4) * 8;
                ldsm4(ah[mi], smaddr(&sAh[r * 40 + cc]));
                ldsm4(al[mi], smaddr(&sAl[r * 40 + cc]));
            }
#pragma unroll
            for (int ni = 0; ni < 4; ni++) {
                int r = wn * 32 + ni * 8 + (lane & 7);
                int cc = kc * 16 + ((lane >> 3) & 1) * 8;
                unsigned bh[2], bl[2];
                ldsm2(bh, smaddr(&sWh[r * 40 + cc]));
                ldsm2(bl, smaddr(&sWl[r * 40 + cc]));
#pragma unroll
                for (int mi = 0; mi < 2; mi++) {
                    mma16816h(acc[mi][ni], ah[mi], bh);
                    mma16816h(acc[mi][ni], ah[mi], bl);
                    mma16816h(acc[mi][ni], al[mi], bh);
                }
            }
        }
    }

#pragma unroll
    for (int mi = 0; mi < 2; mi++)
#pragma unroll
        for (int ni = 0; ni < 4; ni++) {
#pragma unroll
            for (int half = 0; half < 2; half++) {
                int row = m0 + wm * 32 + mi * 16 + (lane >> 2) + half * 8;
                int col = n0 + wn * 32 + ni * 8 + (lane & 3) * 2;
                float v0 = acc[mi][ni][half * 2 + 0];
                float v1 = acc[mi][ni][half * 2 + 1];
                size_t off = (size_t)row * 512 + col;
                if (mode == 1) {
                    *(float2*)&Cf[off] = make_float2(fmaxf(v0, 0.f), fmaxf(v1, 0.f));
                } else if (mode == 2) {
                    *(__half2*)&Cfh[off] = __floats2half2_rn(v0, v1);
                } else {
                    fp16 h0 = __float2half_rn(v0), h1 = __float2half_rn(v1);
                    fp16 l0 = __float2half_rn(v0 - __half2float(h0));
                    fp16 l1 = __float2half_rn(v1 - __half2float(h1));
                    *(__half2*)&Ch[off] = __half2(h0, h1);
                    *(__half2*)&Cl[off] = __half2(l0, l1);
                }
            }
        }
}

// ---- exact score recompute (rare: masked entries near a rintf boundary) ----
__device__ __noinline__ float exact_score(
    const fp16* __restrict__ qh, const fp16* __restrict__ ql,
    const fp16* __restrict__ kh, const fp16* __restrict__ kl,
    int qrow, int krow, int hh)
{
    const fp16* qhp = qh + (size_t)qrow * 512 + hh * 64;
    const fp16* qlp = ql + (size_t)qrow * 512 + hh * 64;
    const fp16* khp = kh + (size_t)krow * 512 + hh * 64;
    const fp16* klp = kl + (size_t)krow * 512 + hh * 64;
    float s = 0.0f;
#pragma unroll 8
    for (int d = 0; d < 64; d++) {
        float qv = __half2float(qhp[d]) + __half2float(qlp[d]);
        float kv = __half2float(khp[d]) + __half2float(klp[d]);
        s = fmaf(qv, kv, s);
    }
    return s;
}

// ---------------- fused attention -----------------------------------------
// CTA: 64 q rows x 8 heads, 512 threads. warp = (head, q-half of 32 rows).
// scores: single fp16-hi mma; masked rintf path with exact correction for
// near-boundary entries; uniform fast path (probs = 1/8) when all heads tie.
#define QSTR 520
#define KVELEM 16640        // K-hi + V, 16x520 fp16 each, per buffer
#define SCH 1088            // floats per head in ssc (64*17)
#define ATH 1536            // halfs per head in sat (64*24)

__global__ __launch_bounds__(512, 1) void fused_attn(
    const fp16* __restrict__ qhp, const fp16* __restrict__ qlp,
    const fp16* __restrict__ khp, const fp16* __restrict__ klp,
    const fp16* __restrict__ vfp)
{
    extern __shared__ char smem[];
    fp16* kv = (fp16*)smem;                        // 2 x 16640 elems = 66560 B
    float* ssc = (float*)(smem + 66560);           // 8 x 1088 fp32 = 34816 B
    fp16* sat = (fp16*)(smem + 101376);            // 8 x 1536 fp16 = 24576 B

    const int tid = threadIdx.x, lane = tid & 31, w = tid >> 5;
    const int h = w & 7, qhalf = w >> 3;
    const int qt = blockIdx.x, b = blockIdx.y;
    const size_t kvbase = (size_t)b * S_ * D_;
    const int qg0 = qt * 64;
    const int browbase = b * S_;

    // ---- stage Q-hi (64x512, stride 520) into kv area (transient) ----
#pragma unroll
    for (int j = 0; j < 8; j++) {
        int u = tid + j * 512;
        int row = u >> 6, cc = u & 63;
        const fp16* src = qhp + (size_t)(browbase + qg0 + row) * 512 + cc * 8;
        *(uint4*)&kv[row * QSTR + cc * 8] = *(const uint4*)src;
    }
    __syncthreads();

    unsigned qf[2][4][4];
#pragma unroll
    for (int mi = 0; mi < 2; mi++)
#pragma unroll
        for (int dc = 0; dc < 4; dc++) {
            int row = qhalf * 32 + mi * 16 + (lane & 15);
            int col = h * 64 + dc * 16 + (lane >> 4) * 8;
            ldsm4(qf[mi][dc], smaddr(&kv[row * QSTR + col]));
        }
    __syncthreads();    // kv area free for KV streaming

    float cacc[2][8][4];
#pragma unroll
    for (int mi = 0; mi < 2; mi++)
#pragma unroll
        for (int ni = 0; ni < 8; ni++)
#pragma unroll
            for (int c = 0; c < 4; c++) cacc[mi][ni][c] = 0.0f;

    // ---- prefetch iter 0 ----
#pragma unroll
    for (int j = 0; j < 4; j++) {
        int c = tid + j * 512;
        int arr = c >> 10, rem = c & 1023;
        int r = rem >> 6, cc = rem & 63;
        size_t goff = kvbase + (size_t)r * 512 + cc * 8;
        const fp16* src = (arr == 0) ? (khp + goff) : (vfp + goff);
        cpa16(smaddr(kv + arr * 8320 + r * 520 + cc * 8), src);
    }
    cpcommit();

    for (int it = 0; it < 256; it++) {
        fp16* buf = kv + (it & 1) * KVELEM;
        const fp16* Kf = buf;
        const fp16* Vf = buf + 8320;

        cpwait0();
        __syncthreads();

        if (it + 1 < 256) {
            fp16* nb = kv + ((it + 1) & 1) * KVELEM;
            const size_t rowoff = kvbase + (size_t)(it + 1) * 16 * 512;
#pragma unroll
            for (int j = 0; j < 4; j++) {
                int c = tid + j * 512;
                int arr = c >> 10, rem = c & 1023;
                int r = rem >> 6, cc = rem & 63;
                size_t goff = rowoff + (size_t)r * 512 + cc * 8;
                const fp16* src = (arr == 0) ? (khp + goff) : (vfp + goff);
                cpa16(smaddr(nb + arr * 8320 + r * 520 + cc * 8), src);
            }
            cpcommit();
        }

        // ---- scores: 32q x 16k for (head h, qhalf), single fp16 mma ----
        float cs[2][2][4];
#pragma unroll
        for (int mi = 0; mi < 2; mi++)
#pragma unroll
            for (int ni = 0; ni < 2; ni++)
#pragma unroll
                for (int c = 0; c < 4; c++) cs[mi][ni][c] = 0.0f;

#pragma unroll
        for (int dc = 0; dc < 4; dc++) {
            unsigned k2[2][2];
#pragma unroll
            for (int ni = 0; ni < 2; ni++) {
                int kr = ni * 8 + (lane & 7);
                int col = h * 64 + dc * 16 + ((lane >> 3) & 1) * 8;
                ldsm2(k2[ni], smaddr(&Kf[kr * 520 + col]));
            }
#pragma unroll
            for (int mi = 0; mi < 2; mi++)
#pragma unroll
                for (int ni = 0; ni < 2; ni++)
                    mma16816h(cs[mi][ni], qf[mi][dc], k2[ni]);
        }
#pragma unroll
        for (int mi = 0; mi < 2; mi++)
#pragma unroll
            for (int ni = 0; ni < 2; ni++) {
                int row = qhalf * 32 + mi * 16 + (lane >> 2);
                int col = ni * 8 + (lane & 3) * 2;
                float* p0 = &ssc[h * SCH + row * 17 + col];
                p0[0] = cs[mi][ni][0]; p0[1] = cs[mi][ni][1];
                float* p1 = &ssc[h * SCH + (row + 8) * 17 + col];
                p1[0] = cs[mi][ni][2]; p1[1] = cs[mi][ni][3];
            }
        __syncthreads();

        // ---- heads softmax: 1024 (q,k) pairs, 2 per thread ----
#pragma unroll
        for (int rep = 0; rep < 2; rep++) {
            int p = tid + rep * 512;
            int q = p >> 4, kk = p & 15;
            int qg = qg0 + q, kg = it * 16 + kk;

            if (kg > qg) {
                // masked: t[h] = 8*rintf(s/64), exact-corrected near boundaries
                float t[8];
                float tmin, tmax;
#pragma unroll
                for (int hh = 0; hh < 8; hh++) {
                    float s = ssc[hh * SCH + q * 17 + kk];
                    float x = s * 0.015625f;
                    float r = rintf(x);
                    if (fabsf(x - r) > 0.4975f) {
                        float se = exact_score(qhp, qlp, khp, klp,
                                               browbase + qg, browbase + kg, hh);
                        r = rintf(se * 0.015625f);
                    }
                    t[hh] = 8.0f * r;
                    if (hh == 0) { tmin = t[0]; tmax = t[0]; }
                    else { tmin = fminf(tmin, t[hh]); tmax = fmaxf(tmax, t[hh]); }
                }
                if (tmin == tmax) {
                    // uniform: softmax = exactly 1/8 (matches fp32 reference)
#pragma unroll
                    for (int hh = 0; hh < 8; hh++)
                        sat[hh * ATH + q * 24 + kk] = __float2half_rn(0.125f);
                } else {
                    float e[8], sum = 0.0f;
#pragma unroll
                    for (int hh = 0; hh < 8; hh++) {
                        e[hh] = __expf(t[hh] - tmax); sum += e[hh];
                    }
                    float inv = 1.0f / sum;
#pragma unroll
                    for (int hh = 0; hh < 8; hh++)
                        sat[hh * ATH + q * 24 + kk] = __float2half_rn(e[hh] * inv);
                }
            } else {
                float t[8];
#pragma unroll
                for (int hh = 0; hh < 8; hh++)
                    t[hh] = ssc[hh * SCH + q * 17 + kk] * 0.125f;
                float m = t[0];
#pragma unroll
                for (int hh = 1; hh < 8; hh++) m = fmaxf(m, t[hh]);
                float e[8], sum = 0.0f;
#pragma unroll
                for (int hh = 0; hh < 8; hh++) { e[hh] = __expf(t[hh] - m); sum += e[hh]; }
                float inv = 1.0f / sum;
#pragma unroll
                for (int hh = 0; hh < 8; hh++)
                    sat[hh * ATH + q * 24 + kk] = __float2half_rn(e[hh] * inv);
            }
        }
        __syncthreads();

        // ---- PV: single fp16 mma ----
        unsigned af[2][4];
#pragma unroll
        for (int mi = 0; mi < 2; mi++) {
            int row = qhalf * 32 + mi * 16 + (lane & 15);
            ldsm4(af[mi], smaddr(&sat[h * ATH + row * 24 + (lane >> 4) * 8]));
        }
#pragma unroll
        for (int ni = 0; ni < 8; ni++) {
            unsigned v2[2];
            ldsm2t(v2, smaddr(&Vf[(lane & 15) * 520 + h * 64 + ni * 8]));
#pragma unroll
            for (int mi = 0; mi < 2; mi++)
                mma16816h(cacc[mi][ni], af[mi], v2);
        }
    }

    // ---- epilogue: ctx -> fp16 hi/lo ----
#pragma unroll
    for (int mi = 0; mi < 2; mi++)
#pragma unroll
        for (int ni = 0; ni < 8; ni++)
#pragma unroll
            for (int hf = 0; hf < 2; hf++) {
                int row = browbase + qg0 + qhalf * 32 + mi * 16 + (lane >> 2) + hf * 8;
                int col = h * 64 + ni * 8 + (lane & 3) * 2;
                float v0 = cacc[mi][ni][hf * 2 + 0];
                float v1 = cacc[mi][ni][hf * 2 + 1];
                fp16 h0 = __float2half_rn(v0), h1 = __float2half_rn(v1);
                fp16 l0 = __float2half_rn(v0 - __half2float(h0));
                fp16 l1 = __float2half_rn(v1 - __half2float(h1));
                size_t off = (size_t)row * 512 + col;
                *(__half2*)&g_ch[off] = __half2(h0, h1);
                *(__half2*)&g_cl[off] = __half2(l0, l1);
            }
}

// ---------------------------------------------------------------------------
extern "C" void kernel_launch(void* const* d_in, const int* in_sizes, int n_in,
                              void* d_out, int out_size)
{
    const float* x  = (const float*)d_in[0];
    const float* W[4] = {(const float*)d_in[1], (const float*)d_in[2],
                         (const float*)d_in[3], (const float*)d_in[4]};
    float* out = (float*)d_out;

    fp16 *xh, *xl, *wh, *wl, *qh, *ql, *kh, *kl, *vf, *ch, *cl;
    cudaGetSymbolAddress((void**)&xh, g_xh);
    cudaGetSymbolAddress((void**)&xl, g_xl);
    cudaGetSymbolAddress((void**)&wh, g_wh);
    cudaGetSymbolAddress((void**)&wl, g_wl);
    cudaGetSymbolAddress((void**)&qh, g_qh);
    cudaGetSymbolAddress((void**)&ql, g_ql);
    cudaGetSymbolAddress((void**)&kh, g_kh);
    cudaGetSymbolAddress((void**)&kl, g_kl);
    cudaGetSymbolAddress((void**)&vf, g_vf);
    cudaGetSymbolAddress((void**)&ch, g_ch);
    cudaGetSymbolAddress((void**)&cl, g_cl);

    // splits
    split_kernel<<<(M_ * D_) / 256, 256>>>(x, xh, xl, M_ * D_);
    for (int i = 0; i < 4; i++)
        split_kernel<<<(D_ * D_) / 256, 256>>>(W[i], wh + (size_t)i * D_ * D_,
                                               wl + (size_t)i * D_ * D_, D_ * D_);

    dim3 gp(D_ / 64, M_ / 128);   // (8, 64)
    gemm_proj<<<gp, 256>>>(xh, xl, wh, wl, qh, ql, nullptr, nullptr, 0);
    gemm_proj<<<gp, 256>>>(xh, xl, wh + (size_t)1 * D_ * D_, wl + (size_t)1 * D_ * D_,
                           kh, kl, nullptr, nullptr, 0);
    gemm_proj<<<gp, 256>>>(xh, xl, wh + (size_t)2 * D_ * D_, wl + (size_t)2 * D_ * D_,
                           nullptr, nullptr, nullptr, vf, 2);

    cudaFuncSetAttribute(fused_attn, cudaFuncAttributeMaxDynamicSharedMemorySize,
                         125952);
    dim3 ga(S_ / 64, B_);         // (64, 2) = 128 CTAs
    fused_attn<<<ga, 512, 125952>>>(qh, ql, kh, kl, vf);

    gemm_proj<<<gp, 256>>>(ch, cl, wh + (size_t)3 * D_ * D_, wl + (size_t)3 * D_ * D_,
                           nullptr, nullptr, out, nullptr, 1);
}

// round 8
// speedup vs baseline: 1.1173x; 1.1173x over previous
#include <cuda_runtime.h>
#include <cuda_fp16.h>

typedef __half fp16;

#define B_ 2
#define S_ 4096
#define D_ 512
#define M_ (B_ * S_)

// ---------------- scratch (fp16 hi/lo everywhere) ----------------
__device__ fp16 g_xh[(size_t)M_ * D_];
__device__ fp16 g_xl[(size_t)M_ * D_];
__device__ fp16 g_wh[4][D_ * D_];
__device__ fp16 g_wl[4][D_ * D_];
__device__ fp16 g_qh[(size_t)M_ * D_];
__device__ fp16 g_ql[(size_t)M_ * D_];
__device__ fp16 g_kh[(size_t)M_ * D_];
__device__ fp16 g_kl[(size_t)M_ * D_];
__device__ fp16 g_vf[(size_t)M_ * D_];
__device__ fp16 g_ch[(size_t)M_ * D_];
__device__ fp16 g_cl[(size_t)M_ * D_];

// ---------------- ptx helpers ----------------
__device__ __forceinline__ unsigned smaddr(const void* p) {
    return (unsigned)__cvta_generic_to_shared(p);
}
__device__ __forceinline__ void ldsm4(unsigned* r, unsigned a) {
    asm volatile("ldmatrix.sync.aligned.m8n8.x4.shared.b16 {%0,%1,%2,%3},[%4];"
                 : "=r"(r[0]), "=r"(r[1]), "=r"(r[2]), "=r"(r[3]) : "r"(a));
}
__device__ __forceinline__ void ldsm2(unsigned* r, unsigned a) {
    asm volatile("ldmatrix.sync.aligned.m8n8.x2.shared.b16 {%0,%1},[%2];"
                 : "=r"(r[0]), "=r"(r[1]) : "r"(a));
}
__device__ __forceinline__ void ldsm2t(unsigned* r, unsigned a) {
    asm volatile("ldmatrix.sync.aligned.m8n8.x2.trans.shared.b16 {%0,%1},[%2];"
                 : "=r"(r[0]), "=r"(r[1]) : "r"(a));
}
__device__ __forceinline__ void mma16816h(float* c, const unsigned* a, const unsigned* b) {
    asm volatile(
        "mma.sync.aligned.m16n8k16.row.col.f32.f16.f16.f32 "
        "{%0,%1,%2,%3},{%4,%5,%6,%7},{%8,%9},{%0,%1,%2,%3};"
        : "+f"(c[0]), "+f"(c[1]), "+f"(c[2]), "+f"(c[3])
        : "r"(a[0]), "r"(a[1]), "r"(a[2]), "r"(a[3]), "r"(b[0]), "r"(b[1]));
}
__device__ __forceinline__ void cpa16(unsigned d, const void* g) {
    asm volatile("cp.async.cg.shared.global [%0], [%1], 16;" :: "r"(d), "l"(g));
}
__device__ __forceinline__ void cpcommit() { asm volatile("cp.async.commit_group;"); }
__device__ __forceinline__ void cpwait0()  { asm volatile("cp.async.wait_group 0;" ::: "memory"); }

// ---------------- split fp32 -> fp16 hi/lo ----------------
__global__ __launch_bounds__(256) void split_kernel(
    const float* __restrict__ in, fp16* __restrict__ hi, fp16* __restrict__ lo, int n)
{
    int i = blockIdx.x * 256 + threadIdx.x;
    if (i < n) {
        float v = in[i];
        fp16 h = __float2half_rn(v);
        hi[i] = h;
        lo[i] = __float2half_rn(v - __half2float(h));
    }
}

// ---------------- projection GEMM: C[M,512] = A[M,512] @ W[512,512]^T --------
// 3-term fp16 mma. mode 0: fp16 hi/lo out. mode 1: relu + fp32 out. mode 2: fp16 out.
__global__ __launch_bounds__(256) void gemm_proj(
    const fp16* __restrict__ Ah, const fp16* __restrict__ Al,
    const fp16* __restrict__ Wh, const fp16* __restrict__ Wl,
    fp16* __restrict__ Ch, fp16* __restrict__ Cl,
    float* __restrict__ Cf, fp16* __restrict__ Cfh, int mode)
{
    __shared__ fp16 sAh[128 * 40], sAl[128 * 40], sWh[64 * 40], sWl[64 * 40];

    const int tid = threadIdx.x, lane = tid & 31, warp = tid >> 5;
    const int m0 = blockIdx.y * 128, n0 = blockIdx.x * 64;
    const int wm = warp >> 1, wn = warp & 1;

    float acc[2][4][4];
#pragma unroll
    for (int a = 0; a < 2; a++)
#pragma unroll
        for (int b = 0; b < 4; b++)
#pragma unroll
            for (int c = 0; c < 4; c++) acc[a][b][c] = 0.0f;

    for (int k0 = 0; k0 < 512; k0 += 32) {
        __syncthreads();
#pragma unroll
        for (int j = 0; j < 4; j++) {
            int u = tid + j * 256;
            int half = u >> 9, rem = u & 511;
            int row = rem >> 2, c4 = rem & 3;
            const fp16* src = (half ? Al : Ah) + (size_t)(m0 + row) * 512 + k0 + c4 * 8;
            fp16* dst = (half ? sAl : sAh) + row * 40 + c4 * 8;
            *(uint4*)dst = *(const uint4*)src;
        }
#pragma unroll
        for (int j = 0; j < 2; j++) {
            int u = tid + j * 256;
            int half = u >> 8, rem = u & 255;
            int row = rem >> 2, c4 = rem & 3;
            const fp16* src = (half ? Wl : Wh) + (size_t)(n0 + row) * 512 + k0 + c4 * 8;
            fp16* dst = (half ? sWl : sWh) + row * 40 + c4 * 8;
            *(uint4*)dst = *(const uint4*)src;
        }
        __syncthreads();

#pragma unroll
        for (int kc = 0; kc < 2; kc++) {
            unsigned ah[2][4], al[2][4];
#pragma unroll
            for (int mi = 0; mi < 2; mi++) {
                int r = wm * 32 + mi * 16 + (lane & 15);
                int cc = kc * 16 + (lane >> 4) * 8;
                ldsm4(ah[mi], smaddr(&sAh[r * 40 + cc]));
                ldsm4(al[mi], smaddr(&sAl[r * 40 + cc]));
            }
#pragma unroll
            for (int ni = 0; ni < 4; ni++) {
                int r = wn * 32 + ni * 8 + (lane & 7);
                int cc = kc * 16 + ((lane >> 3) & 1) * 8;
                unsigned bh[2], bl[2];
                ldsm2(bh, smaddr(&sWh[r * 40 + cc]));
                ldsm2(bl, smaddr(&sWl[r * 40 + cc]));
#pragma unroll
                for (int mi = 0; mi < 2; mi++) {
                    mma16816h(acc[mi][ni], ah[mi], bh);
                    mma16816h(acc[mi][ni], ah[mi], bl);
                    mma16816h(acc[mi][ni], al[mi], bh);
                }
            }
        }
    }

#pragma unroll
    for (int mi = 0; mi < 2; mi++)
#pragma unroll
        for (int ni = 0; ni < 4; ni++) {
#pragma unroll
            for (int half = 0; half < 2; half++) {
                int row = m0 + wm * 32 + mi * 16 + (lane >> 2) + half * 8;
                int col = n0 + wn * 32 + ni * 8 + (lane & 3) * 2;
                float v0 = acc[mi][ni][half * 2 + 0];
                float v1 = acc[mi][ni][half * 2 + 1];
                size_t off = (size_t)row * 512 + col;
                if (mode == 1) {
                    *(float2*)&Cf[off] = make_float2(fmaxf(v0, 0.f), fmaxf(v1, 0.f));
                } else if (mode == 2) {
                    *(__half2*)&Cfh[off] = __floats2half2_rn(v0, v1);
                } else {
                    fp16 h0 = __float2half_rn(v0), h1 = __float2half_rn(v1);
                    fp16 l0 = __float2half_rn(v0 - __half2float(h0));
                    fp16 l1 = __float2half_rn(v1 - __half2float(h1));
                    *(__half2*)&Ch[off] = __half2(h0, h1);
                    *(__half2*)&Cl[off] = __half2(l0, l1);
                }
            }
        }
}

// ---------------- fused attention -----------------------------------------
// CTA: 64 q rows x 8 heads, 512 threads. warp = (head, q-half of 32 rows).
// scores: single fp16-hi mma. Masked path: branchless rintf select + bitmask
// of near-boundary heads; ONE rare branch does the exact fp32 recompute.
// Tie shortcut (all masked logits equal -> 1/8) skips the 8-exp MUFU block.
#define QSTR 520
#define KVELEM 16640        // K-hi + V, 16x520 fp16 each, per buffer
#define SCH 1088            // floats per head in ssc (64*17)
#define ATH 1536            // halfs per head in sat (64*24)

__global__ __launch_bounds__(512, 1) void fused_attn(
    const fp16* __restrict__ qhp, const fp16* __restrict__ qlp,
    const fp16* __restrict__ khp, const fp16* __restrict__ klp,
    const fp16* __restrict__ vfp)
{
    extern __shared__ char smem[];
    fp16* kv = (fp16*)smem;                        // 2 x 16640 elems = 66560 B
    float* ssc = (float*)(smem + 66560);           // 8 x 1088 fp32 = 34816 B
    fp16* sat = (fp16*)(smem + 101376);            // 8 x 1536 fp16 = 24576 B

    const int tid = threadIdx.x, lane = tid & 31, w = tid >> 5;
    const int h = w & 7, qhalf = w >> 3;
    const int qt = blockIdx.x, b = blockIdx.y;
    const size_t kvbase = (size_t)b * S_ * D_;
    const int qg0 = qt * 64;
    const int browbase = b * S_;

    // ---- stage Q-hi (64x512, stride 520) into kv area (transient) ----
#pragma unroll
    for (int j = 0; j < 8; j++) {
        int u = tid + j * 512;
        int row = u >> 6, cc = u & 63;
        const fp16* src = qhp + (size_t)(browbase + qg0 + row) * 512 + cc * 8;
        *(uint4*)&kv[row * QSTR + cc * 8] = *(const uint4*)src;
    }
    __syncthreads();

    unsigned qf[2][4][4];
#pragma unroll
    for (int mi = 0; mi < 2; mi++)
#pragma unroll
        for (int dc = 0; dc < 4; dc++) {
            int row = qhalf * 32 + mi * 16 + (lane & 15);
            int col = h * 64 + dc * 16 + (lane >> 4) * 8;
            ldsm4(qf[mi][dc], smaddr(&kv[row * QSTR + col]));
        }
    __syncthreads();    // kv area free for KV streaming

    float cacc[2][8][4];
#pragma unroll
    for (int mi = 0; mi < 2; mi++)
#pragma unroll
        for (int ni = 0; ni < 8; ni++)
#pragma unroll
            for (int c = 0; c < 4; c++) cacc[mi][ni][c] = 0.0f;

    // ---- prefetch iter 0 ----
#pragma unroll
    for (int j = 0; j < 4; j++) {
        int c = tid + j * 512;
        int arr = c >> 10, rem = c & 1023;
        int r = rem >> 6, cc = rem & 63;
        size_t goff = kvbase + (size_t)r * 512 + cc * 8;
        const fp16* src = (arr == 0) ? (khp + goff) : (vfp + goff);
        cpa16(smaddr(kv + arr * 8320 + r * 520 + cc * 8), src);
    }
    cpcommit();

    for (int it = 0; it < 256; it++) {
        fp16* buf = kv + (it & 1) * KVELEM;
        const fp16* Kf = buf;
        const fp16* Vf = buf + 8320;

        cpwait0();
        __syncthreads();

        if (it + 1 < 256) {
            fp16* nb = kv + ((it + 1) & 1) * KVELEM;
            const size_t rowoff = kvbase + (size_t)(it + 1) * 16 * 512;
#pragma unroll
            for (int j = 0; j < 4; j++) {
                int c = tid + j * 512;
                int arr = c >> 10, rem = c & 1023;
                int r = rem >> 6, cc = rem & 63;
                size_t goff = rowoff + (size_t)r * 512 + cc * 8;
                const fp16* src = (arr == 0) ? (khp + goff) : (vfp + goff);
                cpa16(smaddr(nb + arr * 8320 + r * 520 + cc * 8), src);
            }
            cpcommit();
        }

        // ---- scores: 32q x 16k for (head h, qhalf), single fp16 mma ----
        float cs[2][2][4];
#pragma unroll
        for (int mi = 0; mi < 2; mi++)
#pragma unroll
            for (int ni = 0; ni < 2; ni++)
#pragma unroll
                for (int c = 0; c < 4; c++) cs[mi][ni][c] = 0.0f;

#pragma unroll
        for (int dc = 0; dc < 4; dc++) {
            unsigned k2[2][2];
#pragma unroll
            for (int ni = 0; ni < 2; ni++) {
                int kr = ni * 8 + (lane & 7);
                int col = h * 64 + dc * 16 + ((lane >> 3) & 1) * 8;
                ldsm2(k2[ni], smaddr(&Kf[kr * 520 + col]));
            }
#pragma unroll
            for (int mi = 0; mi < 2; mi++)
#pragma unroll
                for (int ni = 0; ni < 2; ni++)
                    mma16816h(cs[mi][ni], qf[mi][dc], k2[ni]);
        }
#pragma unroll
        for (int mi = 0; mi < 2; mi++)
#pragma unroll
            for (int ni = 0; ni < 2; ni++) {
                int row = qhalf * 32 + mi * 16 + (lane >> 2);
                int col = ni * 8 + (lane & 3) * 2;
                float* p0 = &ssc[h * SCH + row * 17 + col];
                p0[0] = cs[mi][ni][0]; p0[1] = cs[mi][ni][1];
                float* p1 = &ssc[h * SCH + (row + 8) * 17 + col];
                p1[0] = cs[mi][ni][2]; p1[1] = cs[mi][ni][3];
            }
        __syncthreads();

        // ---- heads softmax: 1024 (q,k) pairs, 2 per thread ----
#pragma unroll
        for (int rep = 0; rep < 2; rep++) {
            int p = tid + rep * 512;
            int q = p >> 4, kk = p & 15;
            int qg = qg0 + q, kg = it * 16 + kk;
            bool masked = kg > qg;

            float t[8];
            unsigned bad = 0;
            float tmin = 1e30f, tmax = -1e30f;
#pragma unroll
            for (int hh = 0; hh < 8; hh++) {
                float s = ssc[hh * SCH + q * 17 + kk];
                float x = s * 0.015625f;
                float r = rintf(x);
                t[hh] = masked ? 8.0f * r : s * 0.125f;
                bool nb = masked & (fabsf(x - r) > 0.4975f);
                bad |= nb ? (1u << hh) : 0u;
                tmin = fminf(tmin, t[hh]);
                tmax = fmaxf(tmax, t[hh]);
            }
            if (bad) {      // ~2900 times across the whole launch
#pragma unroll 1
                for (int hh = 0; hh < 8; hh++) {
                    if (bad & (1u << hh)) {
                        const fp16* qhr = qhp + (size_t)(browbase + qg) * 512 + hh * 64;
                        const fp16* qlr = qlp + (size_t)(browbase + qg) * 512 + hh * 64;
                        const fp16* khr = khp + (size_t)(browbase + kg) * 512 + hh * 64;
                        const fp16* klr = klp + (size_t)(browbase + kg) * 512 + hh * 64;
                        float se = 0.0f;
#pragma unroll 8
                        for (int d = 0; d < 64; d++) {
                            float qv = __half2float(qhr[d]) + __half2float(qlr[d]);
                            float kvv = __half2float(khr[d]) + __half2float(klr[d]);
                            se = fmaf(qv, kvv, se);
                        }
                        t[hh] = 8.0f * rintf(se * 0.015625f);
                    }
                }
                tmin = t[0]; tmax = t[0];
#pragma unroll
                for (int hh = 1; hh < 8; hh++) {
                    tmin = fminf(tmin, t[hh]);
                    tmax = fmaxf(tmax, t[hh]);
                }
            }

            if (tmin == tmax) {
                // ties: softmax is exactly 1/8 (identical to full exp path)
#pragma unroll
                for (int hh = 0; hh < 8; hh++)
                    sat[hh * ATH + q * 24 + kk] = __float2half_rn(0.125f);
            } else {
                float e[8], sum = 0.0f;
#pragma unroll
                for (int hh = 0; hh < 8; hh++) { e[hh] = __expf(t[hh] - tmax); sum += e[hh]; }
                float inv = 1.0f / sum;
#pragma unroll
                for (int hh = 0; hh < 8; hh++)
                    sat[hh * ATH + q * 24 + kk] = __float2half_rn(e[hh] * inv);
            }
        }
        __syncthreads();

        // ---- PV: single fp16 mma ----
        unsigned af[2][4];
#pragma unroll
        for (int mi = 0; mi < 2; mi++) {
            int row = qhalf * 32 + mi * 16 + (lane & 15);
            ldsm4(af[mi], smaddr(&sat[h * ATH + row * 24 + (lane >> 4) * 8]));
        }
#pragma unroll
        for (int ni = 0; ni < 8; ni++) {
            unsigned v2[2];
            ldsm2t(v2, smaddr(&Vf[(lane & 15) * 520 + h * 64 + ni * 8]));
#pragma unroll
            for (int mi = 0; mi < 2; mi++)
                mma16816h(cacc[mi][ni], af[mi], v2);
        }
    }

    // ---- epilogue: ctx -> fp16 hi/lo ----
#pragma unroll
    for (int mi = 0; mi < 2; mi++)
#pragma unroll
        for (int ni = 0; ni < 8; ni++)
#pragma unroll
            for (int hf = 0; hf < 2; hf++) {
                int row = browbase + qg0 + qhalf * 32 + mi * 16 + (lane >> 2) + hf * 8;
                int col = h * 64 + ni * 8 + (lane & 3) * 2;
                float v0 = cacc[mi][ni][hf * 2 + 0];
                float v1 = cacc[mi][ni][hf * 2 + 1];
                fp16 h0 = __float2half_rn(v0), h1 = __float2half_rn(v1);
                fp16 l0 = __float2half_rn(v0 - __half2float(h0));
                fp16 l1 = __float2half_rn(v1 - __half2float(h1));
                size_t off = (size_t)row * 512 + col;
                *(__half2*)&g_ch[off] = __half2(h0, h1);
                *(__half2*)&g_cl[off] = __half2(l0, l1);
            }
}

// ---------------------------------------------------------------------------
extern "C" void kernel_launch(void* const* d_in, const int* in_sizes, int n_in,
                              void* d_out, int out_size)
{
    const float* x  = (const float*)d_in[0];
    const float* W[4] = {(const float*)d_in[1], (const float*)d_in[2],
                         (const float*)d_in[3], (const float*)d_in[4]};
    float* out = (float*)d_out;

    fp16 *xh, *xl, *wh, *wl, *qh, *ql, *kh, *kl, *vf, *ch, *cl;
    cudaGetSymbolAddress((void**)&xh, g_xh);
    cudaGetSymbolAddress((void**)&xl, g_xl);
    cudaGetSymbolAddress((void**)&wh, g_wh);
    cudaGetSymbolAddress((void**)&wl, g_wl);
    cudaGetSymbolAddress((void**)&qh, g_qh);
    cudaGetSymbolAddress((void**)&ql, g_ql);
    cudaGetSymbolAddress((void**)&kh, g_kh);
    cudaGetSymbolAddress((void**)&kl, g_kl);
    cudaGetSymbolAddress((void**)&vf, g_vf);
    cudaGetSymbolAddress((void**)&ch, g_ch);
    cudaGetSymbolAddress((void**)&cl, g_cl);

    // splits
    split_kernel<<<(M_ * D_) / 256, 256>>>(x, xh, xl, M_ * D_);
    for (int i = 0; i < 4; i++)
        split_kernel<<<(D_ * D_) / 256, 256>>>(W[i], wh + (size_t)i * D_ * D_,
                                               wl + (size_t)i * D_ * D_, D_ * D_);

    dim3 gp(D_ / 64, M_ / 128);   // (8, 64)
    gemm_proj<<<gp, 256>>>(xh, xl, wh, wl, qh, ql, nullptr, nullptr, 0);
    gemm_proj<<<gp, 256>>>(xh, xl, wh + (size_t)1 * D_ * D_, wl + (size_t)1 * D_ * D_,
                           kh, kl, nullptr, nullptr, 0);
    gemm_proj<<<gp, 256>>>(xh, xl, wh + (size_t)2 * D_ * D_, wl + (size_t)2 * D_ * D_,
                           nullptr, nullptr, nullptr, vf, 2);

    cudaFuncSetAttribute(fused_attn, cudaFuncAttributeMaxDynamicSharedMemorySize,
                         125952);
    dim3 ga(S_ / 64, B_);         // (64, 2) = 128 CTAs
    fused_attn<<<ga, 512, 125952>>>(qh, ql, kh, kl, vf);

    gemm_proj<<<gp, 256>>>(ch, cl, wh + (size_t)3 * D_ * D_, wl + (size_t)3 * D_ * D_,
                           nullptr, nullptr, out, nullptr, 1);
}